// round 1
// baseline (speedup 1.0000x reference)
#include <cuda_runtime.h>
#include <math.h>

#define DIM  1024
#define HID  2048
#define NE   8
#define TOPK 2
#define MAXT 4096
#define MAXSLOTS (MAXT*TOPK)

// ---------------- scratch (static device globals; no allocation) ----------------
__device__ int   g_counts[NE];
__device__ int   g_offsets[NE+1];
__device__ int   g_fill[NE];
__device__ int   g_tok_e[MAXT*TOPK];
__device__ float g_tok_w[MAXT*TOPK];
__device__ int   g_slot_tok[MAXSLOTS];
__device__ float g_slot_w[MAXSLOTS];
__device__ float g_H[(size_t)MAXSLOTS*HID];   // 64 MB: silu(xW1)*xW3 per (token,expert) slot

// ---------------- init: zero output + counters ----------------
__global__ void k_init(float* out, int outN) {
    int i = blockIdx.x * blockDim.x + threadIdx.x;
    if (i < outN) out[i] = 0.f;
    if (i < NE) { g_counts[i] = 0; g_fill[i] = 0; }
}

// ---------------- routing: scores = x@Wg, top-2, softmax ----------------
__global__ void k_route(const float* __restrict__ x, const float* __restrict__ Wg, int T) {
    int warp = (blockIdx.x * blockDim.x + threadIdx.x) >> 5;
    int lane = threadIdx.x & 31;
    if (warp >= T) return;
    const float* xr = x + (size_t)warp * DIM;

    float acc[NE];
#pragma unroll
    for (int e = 0; e < NE; e++) acc[e] = 0.f;

    for (int i = lane; i < DIM; i += 32) {
        float xv = xr[i];
        const float* wg = Wg + (size_t)i * NE;
#pragma unroll
        for (int e = 0; e < NE; e++) acc[e] += xv * wg[e];
    }
#pragma unroll
    for (int off = 16; off > 0; off >>= 1) {
#pragma unroll
        for (int e = 0; e < NE; e++)
            acc[e] += __shfl_down_sync(0xffffffffu, acc[e], off);
    }
    if (lane == 0) {
        int i0 = 0; float s0 = acc[0];
#pragma unroll
        for (int e = 1; e < NE; e++) if (acc[e] > s0) { s0 = acc[e]; i0 = e; }
        int i1 = -1; float s1 = -1e30f;
#pragma unroll
        for (int e = 0; e < NE; e++) if (e != i0 && acc[e] > s1) { s1 = acc[e]; i1 = e; }
        float e1 = expf(s1 - s0);
        float inv = 1.f / (1.f + e1);
        g_tok_e[warp*2+0] = i0;  g_tok_w[warp*2+0] = inv;
        g_tok_e[warp*2+1] = i1;  g_tok_w[warp*2+1] = e1 * inv;
        atomicAdd(&g_counts[i0], 1);
        atomicAdd(&g_counts[i1], 1);
    }
}

// ---------------- offsets: tiny prefix sum ----------------
__global__ void k_offsets() {
    int s = 0; g_offsets[0] = 0;
#pragma unroll
    for (int e = 0; e < NE; e++) { s += g_counts[e]; g_offsets[e+1] = s; }
}

// ---------------- scatter tokens into contiguous per-expert slots ----------------
__global__ void k_scatter(int T) {
    int t = blockIdx.x * blockDim.x + threadIdx.x;
    if (t >= T) return;
#pragma unroll
    for (int k = 0; k < TOPK; k++) {
        int e = g_tok_e[t*2+k];
        int pos = atomicAdd(&g_fill[e], 1);
        int slot = g_offsets[e] + pos;
        g_slot_tok[slot] = t;
        g_slot_w[slot]   = g_tok_w[t*2+k];
    }
}

// ---------------- GEMM1: H = silu(Xg @ W1[e]) * (Xg @ W3[e]) ----------------
// tile: 128 rows (gathered tokens) x 64 cols of HID, computed for W1 and W3 together.
__global__ __launch_bounds__(256) void k_gemm1(
    const float* __restrict__ x,
    const float* __restrict__ W1,
    const float* __restrict__ W3)
{
    const int BM = 128, BN = 64, BK = 16;
    int e    = blockIdx.y >> 5;
    int rt   = blockIdx.y & 31;
    int n_e  = g_counts[e];
    int row0 = rt * BM;
    if (row0 >= n_e) return;
    int base = g_offsets[e];
    int col0 = blockIdx.x * BN;

    __shared__ float As [BK][BM + 4];
    __shared__ float B1s[BK][BN];
    __shared__ float B3s[BK][BN];
    __shared__ int   toks[BM];

    int tid = threadIdx.x;
    if (tid < BM) {
        int r = row0 + tid;
        toks[tid] = (r < n_e) ? g_slot_tok[base + r] : -1;
    }
    __syncthreads();

    float acc1[8][4] = {}, acc3[8][4] = {};
    int tr = tid >> 4, tc = tid & 15;   // tr: 16 row groups of 8; tc: 16 col groups of 4

    const float* W1b = W1 + (size_t)e * DIM * HID + col0;
    const float* W3b = W3 + (size_t)e * DIM * HID + col0;

    for (int k0 = 0; k0 < DIM; k0 += BK) {
        // A: 128x16, 512 float4 tasks, 2/thread
#pragma unroll
        for (int i = 0; i < 2; i++) {
            int task = tid + 256 * i;
            int r = task >> 2, c4 = task & 3;
            int tok = toks[r];
            float4 v = make_float4(0.f,0.f,0.f,0.f);
            if (tok >= 0)
                v = *reinterpret_cast<const float4*>(x + (size_t)tok * DIM + k0 + c4 * 4);
            As[c4*4+0][r] = v.x; As[c4*4+1][r] = v.y;
            As[c4*4+2][r] = v.z; As[c4*4+3][r] = v.w;
        }
        // B1/B3: 16x64 each, one float4 per thread per matrix
        {
            int kk = tid >> 4, c4 = tid & 15;
            float4 v1 = *reinterpret_cast<const float4*>(W1b + (size_t)(k0+kk) * HID + c4 * 4);
            float4 v3 = *reinterpret_cast<const float4*>(W3b + (size_t)(k0+kk) * HID + c4 * 4);
            *reinterpret_cast<float4*>(&B1s[kk][c4*4]) = v1;
            *reinterpret_cast<float4*>(&B3s[kk][c4*4]) = v3;
        }
        __syncthreads();

#pragma unroll
        for (int kk = 0; kk < BK; kk++) {
            float a[8], b1[4], b3[4];
#pragma unroll
            for (int m = 0; m < 8; m++) a[m] = As[kk][tr*8+m];
            *reinterpret_cast<float4*>(b1) = *reinterpret_cast<float4*>(&B1s[kk][tc*4]);
            *reinterpret_cast<float4*>(b3) = *reinterpret_cast<float4*>(&B3s[kk][tc*4]);
#pragma unroll
            for (int m = 0; m < 8; m++)
#pragma unroll
                for (int n = 0; n < 4; n++) {
                    acc1[m][n] += a[m] * b1[n];
                    acc3[m][n] += a[m] * b3[n];
                }
        }
        __syncthreads();
    }

#pragma unroll
    for (int m = 0; m < 8; m++) {
        int r = row0 + tr*8 + m;
        if (r >= n_e) continue;
        float* hrow = g_H + (size_t)(base + r) * HID + col0 + tc * 4;
#pragma unroll
        for (int n = 0; n < 4; n++) {
            float z = acc1[m][n];
            float h = z / (1.f + expf(-z)) * acc3[m][n];
            hrow[n] = h;
        }
    }
}

// ---------------- GEMM2: out[tok] += w * (H @ W2[e]) ----------------
// tile: 128 slot-rows x 128 cols of DIM. atomicAdd (exactly 2 adds per out elem).
__global__ __launch_bounds__(256) void k_gemm2(
    const float* __restrict__ W2,
    float* __restrict__ out)
{
    const int BM = 128, BN = 128, BK = 16;
    int e    = blockIdx.y >> 5;
    int rt   = blockIdx.y & 31;
    int n_e  = g_counts[e];
    int row0 = rt * BM;
    if (row0 >= n_e) return;
    int base = g_offsets[e];
    int col0 = blockIdx.x * BN;

    __shared__ float As[BK][BM + 4];
    __shared__ float Bs[BK][BN];

    int tid = threadIdx.x;
    float acc[8][8] = {};
    int tr = tid >> 4, tc = tid & 15;

    const float* W2b = W2 + (size_t)e * HID * DIM + col0;

    for (int k0 = 0; k0 < HID; k0 += BK) {
        // A: H rows are contiguous per expert; 128x16 = 512 float4, 2/thread
#pragma unroll
        for (int i = 0; i < 2; i++) {
            int task = tid + 256 * i;
            int r = task >> 2, c4 = task & 3;
            int rr = row0 + r;
            float4 v = make_float4(0.f,0.f,0.f,0.f);
            if (rr < n_e)
                v = *reinterpret_cast<const float4*>(g_H + (size_t)(base + rr) * HID + k0 + c4 * 4);
            As[c4*4+0][r] = v.x; As[c4*4+1][r] = v.y;
            As[c4*4+2][r] = v.z; As[c4*4+3][r] = v.w;
        }
        // B: 16x128 = 512 float4, 2/thread
#pragma unroll
        for (int i = 0; i < 2; i++) {
            int task = tid + 256 * i;
            int kk = task >> 5, c4 = task & 31;
            float4 v = *reinterpret_cast<const float4*>(W2b + (size_t)(k0+kk) * DIM + c4 * 4);
            *reinterpret_cast<float4*>(&Bs[kk][c4*4]) = v;
        }
        __syncthreads();

#pragma unroll
        for (int kk = 0; kk < BK; kk++) {
            float a[8], b[8];
#pragma unroll
            for (int m = 0; m < 8; m++) a[m] = As[kk][tr*8+m];
            *reinterpret_cast<float4*>(&b[0]) = *reinterpret_cast<float4*>(&Bs[kk][tc*8]);
            *reinterpret_cast<float4*>(&b[4]) = *reinterpret_cast<float4*>(&Bs[kk][tc*8+4]);
#pragma unroll
            for (int m = 0; m < 8; m++)
#pragma unroll
                for (int n = 0; n < 8; n++)
                    acc[m][n] += a[m] * b[n];
        }
        __syncthreads();
    }

#pragma unroll
    for (int m = 0; m < 8; m++) {
        int r = row0 + tr*8 + m;
        if (r >= n_e) continue;
        float w  = g_slot_w[base + r];
        int  tok = g_slot_tok[base + r];
        float* orow = out + (size_t)tok * DIM + col0 + tc * 8;
#pragma unroll
        for (int n = 0; n < 8; n++)
            atomicAdd(&orow[n], w * acc[m][n]);
    }
}

// ---------------- launch ----------------
extern "C" void kernel_launch(void* const* d_in, const int* in_sizes, int n_in,
                              void* d_out, int out_size)
{
    const float* x  = (const float*)d_in[0];
    const float* Wg = (const float*)d_in[1];
    const float* W1 = (const float*)d_in[2];
    const float* W3 = (const float*)d_in[3];
    const float* W2 = (const float*)d_in[4];
    float* out = (float*)d_out;

    int T = in_sizes[0] / DIM;   // 4096

    // 1) zero out + counters
    {
        int n = out_size;
        int blocks = (n + 255) / 256;
        k_init<<<blocks, 256>>>(out, n);
    }
    // 2) routing (1 warp per token)
    {
        int blocks = (T + 3) / 4;
        k_route<<<blocks, 128>>>(x, Wg, T);
    }
    // 3) offsets
    k_offsets<<<1, 1>>>();
    // 4) scatter
    k_scatter<<<(T + 255) / 256, 256>>>(T);
    // 5) GEMM1: grid (HID/64, NE * MAXT/128), early-exit for empty tiles
    {
        dim3 grid(HID / 64, NE * (MAXT / 128));
        k_gemm1<<<grid, 256>>>(x, W1, W3);
    }
    // 6) GEMM2: grid (DIM/128, NE * MAXT/128)
    {
        dim3 grid(DIM / 128, NE * (MAXT / 128));
        k_gemm2<<<grid, 256>>>(W2, out);
    }
}

// round 3
// speedup vs baseline: 2.9450x; 2.9450x over previous
#include <cuda_runtime.h>
#include <math.h>
#include <stdint.h>

#define DIM  1024
#define HID  2048
#define NE   8
#define MAXT 4096
#define MAXSLOTS (MAXT*2)

// ---------------- device scratch ----------------
__device__ int   g_counts[NE];
__device__ int   g_offsets[NE+1];
__device__ int   g_fill[NE];
__device__ int   g_tok_e[MAXT*2];
__device__ float g_tok_w[MAXT*2];
__device__ int   g_slot_tok[MAXSLOTS];
__device__ float g_slot_w[MAXSLOTS];
__device__ float g_Xr[(size_t)MAXT*DIM];      // 16 MB tf32-rounded x
__device__ float g_H[(size_t)MAXSLOTS*HID];   // 64 MB
__device__ float g_W1T[(size_t)NE*HID*DIM];   // [E][HID][DIM] k-major
__device__ float g_W3T[(size_t)NE*HID*DIM];
__device__ float g_W2T[(size_t)NE*DIM*HID];   // [E][DIM][HID] k-major

// ---------------- helpers ----------------
__device__ __forceinline__ float tf32r(float f) {
    uint32_t u;
    asm("cvt.rna.tf32.f32 %0, %1;" : "=r"(u) : "f"(f));
    return __uint_as_float(u);
}
__device__ __forceinline__ uint32_t smem_u32(const void* p) {
    uint32_t a;
    asm("{ .reg .u64 t; cvta.to.shared.u64 t, %1; cvt.u32.u64 %0, t; }" : "=r"(a) : "l"(p));
    return a;
}
__device__ __forceinline__ void cpa16(uint32_t dst, const void* src, int sz) {
    asm volatile("cp.async.cg.shared.global [%0], [%1], 16, %2;"
                 :: "r"(dst), "l"(src), "r"(sz) : "memory");
}
#define CP_COMMIT() asm volatile("cp.async.commit_group;" ::: "memory")
#define CP_WAIT1()  asm volatile("cp.async.wait_group 1;" ::: "memory")
#define CP_WAIT0()  asm volatile("cp.async.wait_group 0;" ::: "memory")

#define LDSM4(r, addr) \
    asm volatile("ldmatrix.sync.aligned.m8n8.x4.shared.b16 {%0,%1,%2,%3}, [%4];" \
        : "=r"((r)[0]), "=r"((r)[1]), "=r"((r)[2]), "=r"((r)[3]) : "r"(addr))

#define MMA_TF32(d, a, b) \
    asm volatile("mma.sync.aligned.m16n8k8.row.col.f32.tf32.tf32.f32 " \
        "{%0,%1,%2,%3}, {%4,%5,%6,%7}, {%8,%9}, {%0,%1,%2,%3};" \
        : "+f"((d)[0]), "+f"((d)[1]), "+f"((d)[2]), "+f"((d)[3]) \
        : "r"((a)[0]), "r"((a)[1]), "r"((a)[2]), "r"((a)[3]), \
          "r"((b)[0]), "r"((b)[1]))

// ---------------- init ----------------
__global__ void k_init(float* out, int outN) {
    int i = blockIdx.x * blockDim.x + threadIdx.x;
    if (i < outN) out[i] = 0.f;
    if (i < NE) { g_counts[i] = 0; g_fill[i] = 0; }
}

__global__ void k_round_x(const float* __restrict__ x, int n) {
    int i = blockIdx.x * blockDim.x + threadIdx.x;
    if (i < n) g_Xr[i] = tf32r(x[i]);
}

// ---------------- weight transpose (+ tf32 rounding) ----------------
__global__ void k_transpose(const float* __restrict__ in, int sel, int R, int C) {
    __shared__ float tile[32][33];
    float* out = (sel == 0) ? g_W1T : (sel == 1) ? g_W3T : g_W2T;
    int e = blockIdx.z;
    const float* inp = in + (size_t)e * R * C;
    float* outp = out + (size_t)e * R * C;
    int x = blockIdx.x * 32 + threadIdx.x;
    int y0 = blockIdx.y * 32;
#pragma unroll
    for (int j = threadIdx.y; j < 32; j += 8)
        tile[j][threadIdx.x] = inp[(size_t)(y0 + j) * C + x];
    __syncthreads();
    int x2 = y0 + threadIdx.x;
    int y2 = blockIdx.x * 32;
#pragma unroll
    for (int j = threadIdx.y; j < 32; j += 8)
        outp[(size_t)(y2 + j) * R + x2] = tf32r(tile[threadIdx.x][j]);
}

// ---------------- routing ----------------
__global__ void k_route(const float* __restrict__ x, const float* __restrict__ Wg, int T) {
    int warp = (blockIdx.x * blockDim.x + threadIdx.x) >> 5;
    int lane = threadIdx.x & 31;
    if (warp >= T) return;
    const float* xr = x + (size_t)warp * DIM;
    float acc[NE];
#pragma unroll
    for (int e = 0; e < NE; e++) acc[e] = 0.f;
    for (int i = lane; i < DIM; i += 32) {
        float xv = xr[i];
        const float* wg = Wg + (size_t)i * NE;
#pragma unroll
        for (int e = 0; e < NE; e++) acc[e] += xv * wg[e];
    }
#pragma unroll
    for (int off = 16; off > 0; off >>= 1)
#pragma unroll
        for (int e = 0; e < NE; e++)
            acc[e] += __shfl_down_sync(0xffffffffu, acc[e], off);
    if (lane == 0) {
        int i0 = 0; float s0 = acc[0];
#pragma unroll
        for (int e = 1; e < NE; e++) if (acc[e] > s0) { s0 = acc[e]; i0 = e; }
        int i1 = -1; float s1 = -1e30f;
#pragma unroll
        for (int e = 0; e < NE; e++) if (e != i0 && acc[e] > s1) { s1 = acc[e]; i1 = e; }
        float e1 = expf(s1 - s0);
        float inv = 1.f / (1.f + e1);
        g_tok_e[warp*2+0] = i0;  g_tok_w[warp*2+0] = inv;
        g_tok_e[warp*2+1] = i1;  g_tok_w[warp*2+1] = e1 * inv;
        atomicAdd(&g_counts[i0], 1);
        atomicAdd(&g_counts[i1], 1);
    }
}

__global__ void k_offsets() {
    int s = 0; g_offsets[0] = 0;
#pragma unroll
    for (int e = 0; e < NE; e++) { s += g_counts[e]; g_offsets[e+1] = s; }
}

__global__ void k_scatter(int T) {
    int t = blockIdx.x * blockDim.x + threadIdx.x;
    if (t >= T) return;
#pragma unroll
    for (int k = 0; k < 2; k++) {
        int e = g_tok_e[t*2+k];
        int pos = atomicAdd(&g_fill[e], 1);
        int slot = g_offsets[e] + pos;
        g_slot_tok[slot] = t;
        g_slot_w[slot]   = g_tok_w[t*2+k];
    }
}

// ================= GEMM1: H = silu(Xg@W1) * (Xg@W3), mma.sync tf32 =================
// CTA 128m x 64n (for BOTH W1,W3), BK=32, 3-stage cp.async. 8 warps 4x2, warp 32x32.
#define G1_STAGE 32768
#define G1_SMEM  (3*G1_STAGE + 512)

__global__ __launch_bounds__(256) void k_mma1() {
    extern __shared__ char smem[];
    int e    = blockIdx.y >> 5;
    int rt   = blockIdx.y & 31;
    int n_e  = g_counts[e];
    int row0 = rt * 128;
    if (row0 >= n_e) return;
    int base = g_offsets[e];
    int col0 = blockIdx.x * 64;

    uint32_t sb = smem_u32(smem);
    int tid = threadIdx.x, wid = tid >> 5, lane = tid & 31;
    int wm = wid >> 1, wn = wid & 1;
    int gid = lane >> 2, ctid = lane & 3;
    int* toks = (int*)(smem + 3*G1_STAGE);

    if (tid < 128) {
        int r = row0 + tid;
        toks[tid] = (r < n_e) ? g_slot_tok[base + r] : -1;
    }
    __syncthreads();

    const float* B1g = g_W1T + (size_t)e * HID * DIM + (size_t)col0 * DIM;
    const float* B3g = g_W3T + (size_t)e * HID * DIM + (size_t)col0 * DIM;

    float acc1[2][4][4] = {}, acc3[2][4][4] = {};
    const int KT = DIM / 32;

    // prefetch helper (stage buf, k-tile kt)
    auto prefetch = [&](int buf, int kt) {
        int k0 = kt * 32;
        uint32_t sA  = sb + buf * G1_STAGE;
        uint32_t sB1 = sA + 16384;
        uint32_t sB3 = sA + 24576;
#pragma unroll
        for (int i = 0; i < 4; i++) {            // A: 128 rows x 8 chunks
            int task = tid + 256 * i;
            int r = task >> 3, c = task & 7;
            int tok = toks[r];
            const float* src = g_Xr + (size_t)(tok < 0 ? 0 : tok) * DIM + k0 + c * 4;
            cpa16(sA + r * 128 + (((c ^ (r & 7))) << 4), src, tok < 0 ? 0 : 16);
        }
#pragma unroll
        for (int i = 0; i < 2; i++) {            // B1,B3: 64 rows x 8 chunks each
            int task = tid + 256 * i;
            int r = task >> 3, c = task & 7;
            uint32_t off = r * 128 + (((c ^ (r & 7))) << 4);
            cpa16(sB1 + off, B1g + (size_t)r * DIM + k0 + c * 4, 16);
            cpa16(sB3 + off, B3g + (size_t)r * DIM + k0 + c * 4, 16);
        }
    };

    prefetch(0, 0); CP_COMMIT();
    prefetch(1, 1); CP_COMMIT();

    for (int kt = 0; kt < KT; kt++) {
        CP_WAIT1();
        __syncthreads();
        if (kt + 2 < KT) prefetch((kt + 2) % 3, kt + 2);
        CP_COMMIT();

        uint32_t sA  = sb + (kt % 3) * G1_STAGE;
        uint32_t sB1 = sA + 16384;
        uint32_t sB3 = sA + 24576;
        int arow = (lane & 15);
        int achk = (lane >> 4);
#pragma unroll
        for (int k8 = 0; k8 < 4; k8++) {
            int cb = k8 * 2 + achk;
            uint32_t aF[2][4], b1F[4][2], b3F[4][2];
#pragma unroll
            for (int mt = 0; mt < 2; mt++) {
                int row = wm * 32 + mt * 16 + arow;
                LDSM4(aF[mt], sA + row * 128 + ((cb ^ (row & 7)) << 4));
            }
#pragma unroll
            for (int pr = 0; pr < 2; pr++) {
                int row = wn * 32 + pr * 16 + arow;
                uint32_t off = row * 128 + ((cb ^ (row & 7)) << 4);
                uint32_t t1[4], t3[4];
                LDSM4(t1, sB1 + off);
                LDSM4(t3, sB3 + off);
                b1F[pr*2+0][0] = t1[0]; b1F[pr*2+0][1] = t1[2];
                b1F[pr*2+1][0] = t1[1]; b1F[pr*2+1][1] = t1[3];
                b3F[pr*2+0][0] = t3[0]; b3F[pr*2+0][1] = t3[2];
                b3F[pr*2+1][0] = t3[1]; b3F[pr*2+1][1] = t3[3];
            }
#pragma unroll
            for (int mt = 0; mt < 2; mt++)
#pragma unroll
                for (int nt = 0; nt < 4; nt++) {
                    MMA_TF32(acc1[mt][nt], aF[mt], b1F[nt]);
                    MMA_TF32(acc3[mt][nt], aF[mt], b3F[nt]);
                }
        }
        __syncthreads();
    }
    CP_WAIT0();

    // epilogue: h = tf32(silu(z1)*z3) -> g_H
#pragma unroll
    for (int mt = 0; mt < 2; mt++) {
#pragma unroll
        for (int half = 0; half < 2; half++) {
            int r = row0 + wm * 32 + mt * 16 + half * 8 + gid;
            if (r >= n_e) continue;
            float* hrow = g_H + (size_t)(base + r) * HID + col0;
#pragma unroll
            for (int nt = 0; nt < 4; nt++) {
                float z1a = acc1[mt][nt][half*2+0], z1b = acc1[mt][nt][half*2+1];
                float z3a = acc3[mt][nt][half*2+0], z3b = acc3[mt][nt][half*2+1];
                float2 h;
                h.x = tf32r(z1a / (1.f + __expf(-z1a)) * z3a);
                h.y = tf32r(z1b / (1.f + __expf(-z1b)) * z3b);
                *(float2*)(hrow + wn * 32 + nt * 8 + ctid * 2) = h;
            }
        }
    }
}

// ================= GEMM2: out[tok] += w * (H @ W2), mma.sync tf32 =================
// CTA 128m x 64n, BK=32, 3-stage. K = HID = 2048.
#define G2_STAGE 24576
#define G2_SMEM  (3*G2_STAGE)

__global__ __launch_bounds__(256) void k_mma2(float* __restrict__ out) {
    extern __shared__ char smem[];
    int e    = blockIdx.y >> 5;
    int rt   = blockIdx.y & 31;
    int n_e  = g_counts[e];
    int row0 = rt * 128;
    if (row0 >= n_e) return;
    int base = g_offsets[e];
    int col0 = blockIdx.x * 64;

    uint32_t sb = smem_u32(smem);
    int tid = threadIdx.x, wid = tid >> 5, lane = tid & 31;
    int wm = wid >> 1, wn = wid & 1;
    int gid = lane >> 2, ctid = lane & 3;

    const float* Bg = g_W2T + (size_t)e * DIM * HID + (size_t)col0 * HID;

    float acc[2][4][4] = {};
    const int KT = HID / 32;

    auto prefetch = [&](int buf, int kt) {
        int k0 = kt * 32;
        uint32_t sA = sb + buf * G2_STAGE;
        uint32_t sB = sA + 16384;
#pragma unroll
        for (int i = 0; i < 4; i++) {
            int task = tid + 256 * i;
            int r = task >> 3, c = task & 7;
            int rr = row0 + r;
            bool ok = (rr < n_e);
            const float* src = g_H + (size_t)(base + (ok ? rr : 0)) * HID + k0 + c * 4;
            cpa16(sA + r * 128 + (((c ^ (r & 7))) << 4), src, ok ? 16 : 0);
        }
#pragma unroll
        for (int i = 0; i < 2; i++) {
            int task = tid + 256 * i;
            int r = task >> 3, c = task & 7;
            cpa16(sB + r * 128 + (((c ^ (r & 7))) << 4),
                  Bg + (size_t)r * HID + k0 + c * 4, 16);
        }
    };

    prefetch(0, 0); CP_COMMIT();
    prefetch(1, 1); CP_COMMIT();

    for (int kt = 0; kt < KT; kt++) {
        CP_WAIT1();
        __syncthreads();
        if (kt + 2 < KT) prefetch((kt + 2) % 3, kt + 2);
        CP_COMMIT();

        uint32_t sA = sb + (kt % 3) * G2_STAGE;
        uint32_t sB = sA + 16384;
        int arow = (lane & 15);
        int achk = (lane >> 4);
#pragma unroll
        for (int k8 = 0; k8 < 4; k8++) {
            int cb = k8 * 2 + achk;
            uint32_t aF[2][4], bF[4][2];
#pragma unroll
            for (int mt = 0; mt < 2; mt++) {
                int row = wm * 32 + mt * 16 + arow;
                LDSM4(aF[mt], sA + row * 128 + ((cb ^ (row & 7)) << 4));
            }
#pragma unroll
            for (int pr = 0; pr < 2; pr++) {
                int row = wn * 32 + pr * 16 + arow;
                uint32_t t[4];
                LDSM4(t, sB + row * 128 + ((cb ^ (row & 7)) << 4));
                bF[pr*2+0][0] = t[0]; bF[pr*2+0][1] = t[2];
                bF[pr*2+1][0] = t[1]; bF[pr*2+1][1] = t[3];
            }
#pragma unroll
            for (int mt = 0; mt < 2; mt++)
#pragma unroll
                for (int nt = 0; nt < 4; nt++)
                    MMA_TF32(acc[mt][nt], aF[mt], bF[nt]);
        }
        __syncthreads();
    }
    CP_WAIT0();

    // epilogue: out[tok] += w * acc (atomic; exactly 2 contributions per element)
#pragma unroll
    for (int mt = 0; mt < 2; mt++) {
#pragma unroll
        for (int half = 0; half < 2; half++) {
            int r = row0 + wm * 32 + mt * 16 + half * 8 + gid;
            if (r >= n_e) continue;
            float w  = g_slot_w[base + r];
            int  tok = g_slot_tok[base + r];
            float* orow = out + (size_t)tok * DIM + col0;
#pragma unroll
            for (int nt = 0; nt < 4; nt++) {
                int c = wn * 32 + nt * 8 + ctid * 2;
                atomicAdd(&orow[c],     w * acc[mt][nt][half*2+0]);
                atomicAdd(&orow[c + 1], w * acc[mt][nt][half*2+1]);
            }
        }
    }
}

// ---------------- launch ----------------
extern "C" void kernel_launch(void* const* d_in, const int* in_sizes, int n_in,
                              void* d_out, int out_size)
{
    const float* x  = (const float*)d_in[0];
    const float* Wg = (const float*)d_in[1];
    const float* W1 = (const float*)d_in[2];
    const float* W3 = (const float*)d_in[3];
    const float* W2 = (const float*)d_in[4];
    float* out = (float*)d_out;
    int T = in_sizes[0] / DIM;

    cudaFuncSetAttribute(k_mma1, cudaFuncAttributeMaxDynamicSharedMemorySize, G1_SMEM);
    cudaFuncSetAttribute(k_mma2, cudaFuncAttributeMaxDynamicSharedMemorySize, G2_SMEM);

    k_init<<<(out_size + 255) / 256, 256>>>(out, out_size);
    k_round_x<<<(T * DIM + 255) / 256, 256>>>(x, T * DIM);

    k_transpose<<<dim3(HID/32, DIM/32, NE), dim3(32, 8)>>>(W1, 0, DIM, HID);
    k_transpose<<<dim3(HID/32, DIM/32, NE), dim3(32, 8)>>>(W3, 1, DIM, HID);
    k_transpose<<<dim3(DIM/32, HID/32, NE), dim3(32, 8)>>>(W2, 2, HID, DIM);

    k_route<<<(T + 3) / 4, 128>>>(x, Wg, T);
    k_offsets<<<1, 1>>>();
    k_scatter<<<(T + 255) / 256, 256>>>(T);

    k_mma1<<<dim3(HID/64, NE * (MAXT/128)), 256, G1_SMEM>>>();
    k_mma2<<<dim3(DIM/64, NE * (MAXT/128)), 256, G2_SMEM>>>(out);
}

// round 4
// speedup vs baseline: 4.7589x; 1.6159x over previous
#include <cuda_runtime.h>
#include <cuda_fp16.h>
#include <math.h>
#include <stdint.h>

#define DIM  1024
#define HID  2048
#define NE   8
#define MAXT 4096
#define MAXSLOTS (MAXT*2)

// ---------------- device scratch ----------------
__device__ int    g_counts[NE];
__device__ int    g_offsets[NE+1];
__device__ int    g_fill[NE];
__device__ int    g_tok_e[MAXT*2];
__device__ float  g_tok_w[MAXT*2];
__device__ int    g_slot_tok[MAXSLOTS];
__device__ float  g_slot_w[MAXSLOTS];
__device__ __half g_Xh[(size_t)MAXT*DIM];       // 8 MB fp16 x
__device__ __half g_H[(size_t)MAXSLOTS*HID];    // 32 MB fp16 hidden
__device__ __half g_W1T[(size_t)NE*HID*DIM];    // [E][HID][DIM] k-major fp16
__device__ __half g_W3T[(size_t)NE*HID*DIM];
__device__ __half g_W2T[(size_t)NE*DIM*HID];    // [E][DIM][HID] k-major fp16

// ---------------- helpers ----------------
__device__ __forceinline__ uint32_t smem_u32(const void* p) {
    uint32_t a;
    asm("{ .reg .u64 t; cvta.to.shared.u64 t, %1; cvt.u32.u64 %0, t; }" : "=r"(a) : "l"(p));
    return a;
}
__device__ __forceinline__ void cpa16(uint32_t dst, const void* src, int sz) {
    asm volatile("cp.async.cg.shared.global [%0], [%1], 16, %2;"
                 :: "r"(dst), "l"(src), "r"(sz) : "memory");
}
#define CP_COMMIT() asm volatile("cp.async.commit_group;" ::: "memory")
#define CP_WAIT1()  asm volatile("cp.async.wait_group 1;" ::: "memory")
#define CP_WAIT0()  asm volatile("cp.async.wait_group 0;" ::: "memory")

#define LDSM4(r, addr) \
    asm volatile("ldmatrix.sync.aligned.m8n8.x4.shared.b16 {%0,%1,%2,%3}, [%4];" \
        : "=r"((r)[0]), "=r"((r)[1]), "=r"((r)[2]), "=r"((r)[3]) : "r"(addr))

#define MMA_F16(d, a, b) \
    asm volatile("mma.sync.aligned.m16n8k16.row.col.f32.f16.f16.f32 " \
        "{%0,%1,%2,%3}, {%4,%5,%6,%7}, {%8,%9}, {%0,%1,%2,%3};" \
        : "+f"((d)[0]), "+f"((d)[1]), "+f"((d)[2]), "+f"((d)[3]) \
        : "r"((a)[0]), "r"((a)[1]), "r"((a)[2]), "r"((a)[3]), \
          "r"((b)[0]), "r"((b)[1]))

// ---------------- init ----------------
__global__ void k_init(float* out, int outN) {
    int i = blockIdx.x * blockDim.x + threadIdx.x;
    if (i < outN) out[i] = 0.f;
    if (i < NE) { g_counts[i] = 0; g_fill[i] = 0; }
}

__global__ void k_cvt_x(const float* __restrict__ x, int n) {
    int i = blockIdx.x * blockDim.x + threadIdx.x;
    if (i < n) g_Xh[i] = __float2half(x[i]);
}

// ---------------- weight transpose + fp16 convert ----------------
__global__ void k_transpose(const float* __restrict__ in, int sel, int R, int C) {
    __shared__ float tile[32][33];
    __half* out = (sel == 0) ? g_W1T : (sel == 1) ? g_W3T : g_W2T;
    int e = blockIdx.z;
    const float* inp = in + (size_t)e * R * C;
    __half* outp = out + (size_t)e * R * C;
    int x = blockIdx.x * 32 + threadIdx.x;
    int y0 = blockIdx.y * 32;
#pragma unroll
    for (int j = threadIdx.y; j < 32; j += 8)
        tile[j][threadIdx.x] = inp[(size_t)(y0 + j) * C + x];
    __syncthreads();
    int x2 = y0 + threadIdx.x;
    int y2 = blockIdx.x * 32;
#pragma unroll
    for (int j = threadIdx.y; j < 32; j += 8)
        outp[(size_t)(y2 + j) * R + x2] = __float2half(tile[threadIdx.x][j]);
}

// ---------------- routing (fp32) ----------------
__global__ void k_route(const float* __restrict__ x, const float* __restrict__ Wg, int T) {
    int warp = (blockIdx.x * blockDim.x + threadIdx.x) >> 5;
    int lane = threadIdx.x & 31;
    if (warp >= T) return;
    const float* xr = x + (size_t)warp * DIM;
    float acc[NE];
#pragma unroll
    for (int e = 0; e < NE; e++) acc[e] = 0.f;
    for (int i = lane; i < DIM; i += 32) {
        float xv = xr[i];
        const float* wg = Wg + (size_t)i * NE;
#pragma unroll
        for (int e = 0; e < NE; e++) acc[e] += xv * wg[e];
    }
#pragma unroll
    for (int off = 16; off > 0; off >>= 1)
#pragma unroll
        for (int e = 0; e < NE; e++)
            acc[e] += __shfl_down_sync(0xffffffffu, acc[e], off);
    if (lane == 0) {
        int i0 = 0; float s0 = acc[0];
#pragma unroll
        for (int e = 1; e < NE; e++) if (acc[e] > s0) { s0 = acc[e]; i0 = e; }
        int i1 = -1; float s1 = -1e30f;
#pragma unroll
        for (int e = 0; e < NE; e++) if (e != i0 && acc[e] > s1) { s1 = acc[e]; i1 = e; }
        float e1 = expf(s1 - s0);
        float inv = 1.f / (1.f + e1);
        g_tok_e[warp*2+0] = i0;  g_tok_w[warp*2+0] = inv;
        g_tok_e[warp*2+1] = i1;  g_tok_w[warp*2+1] = e1 * inv;
        atomicAdd(&g_counts[i0], 1);
        atomicAdd(&g_counts[i1], 1);
    }
}

__global__ void k_offsets() {
    int s = 0; g_offsets[0] = 0;
#pragma unroll
    for (int e = 0; e < NE; e++) { s += g_counts[e]; g_offsets[e+1] = s; }
}

__global__ void k_scatter(int T) {
    int t = blockIdx.x * blockDim.x + threadIdx.x;
    if (t >= T) return;
#pragma unroll
    for (int k = 0; k < 2; k++) {
        int e = g_tok_e[t*2+k];
        int pos = atomicAdd(&g_fill[e], 1);
        int slot = g_offsets[e] + pos;
        g_slot_tok[slot] = t;
        g_slot_w[slot]   = g_tok_w[t*2+k];
    }
}

// ================= GEMM1: H = silu(Xg@W1) * (Xg@W3), mma.sync fp16 =================
// CTA 128m x 64n (both W1,W3), BK=64 halves, 3-stage cp.async. 8 warps 4x2, warp 32x32.
#define G1_STAGE 32768      // A 16K + B1 8K + B3 8K
#define G1_SMEM  (3*G1_STAGE + 512)

__global__ __launch_bounds__(256) void k_mma1() {
    extern __shared__ char smem[];
    int e    = blockIdx.y >> 5;
    int rt   = blockIdx.y & 31;
    int n_e  = g_counts[e];
    int row0 = rt * 128;
    if (row0 >= n_e) return;
    int base = g_offsets[e];
    int col0 = blockIdx.x * 64;

    uint32_t sb = smem_u32(smem);
    int tid = threadIdx.x, wid = tid >> 5, lane = tid & 31;
    int wm = wid >> 1, wn = wid & 1;
    int gid = lane >> 2, ctid = lane & 3;
    int* toks = (int*)(smem + 3*G1_STAGE);

    if (tid < 128) {
        int r = row0 + tid;
        toks[tid] = (r < n_e) ? g_slot_tok[base + r] : -1;
    }
    __syncthreads();

    const __half* B1g = g_W1T + (size_t)e * HID * DIM + (size_t)col0 * DIM;
    const __half* B3g = g_W3T + (size_t)e * HID * DIM + (size_t)col0 * DIM;

    float acc1[2][4][4] = {}, acc3[2][4][4] = {};
    const int KT = DIM / 64;

    auto prefetch = [&](int buf, int kt) {
        int k0 = kt * 64;
        uint32_t sA  = sb + buf * G1_STAGE;
        uint32_t sB1 = sA + 16384;
        uint32_t sB3 = sA + 24576;
#pragma unroll
        for (int i = 0; i < 4; i++) {            // A: 128 rows x 8 chunks of 8 halves
            int task = tid + 256 * i;
            int r = task >> 3, c = task & 7;
            int tok = toks[r];
            const __half* src = g_Xh + (size_t)(tok < 0 ? 0 : tok) * DIM + k0 + c * 8;
            cpa16(sA + r * 128 + ((c ^ (r & 7)) << 4), src, tok < 0 ? 0 : 16);
        }
#pragma unroll
        for (int i = 0; i < 2; i++) {            // B1,B3: 64 rows x 8 chunks each
            int task = tid + 256 * i;
            int r = task >> 3, c = task & 7;
            uint32_t off = r * 128 + ((c ^ (r & 7)) << 4);
            cpa16(sB1 + off, B1g + (size_t)r * DIM + k0 + c * 8, 16);
            cpa16(sB3 + off, B3g + (size_t)r * DIM + k0 + c * 8, 16);
        }
    };

    prefetch(0, 0); CP_COMMIT();
    prefetch(1, 1); CP_COMMIT();

    for (int kt = 0; kt < KT; kt++) {
        CP_WAIT1();
        __syncthreads();
        if (kt + 2 < KT) prefetch((kt + 2) % 3, kt + 2);
        CP_COMMIT();

        uint32_t sA  = sb + (kt % 3) * G1_STAGE;
        uint32_t sB1 = sA + 16384;
        uint32_t sB3 = sA + 24576;
        int arow = (lane & 15);
        int achk = (lane >> 4);          // 0/1 -> k8 sub-tile
#pragma unroll
        for (int s = 0; s < 4; s++) {    // 4 x k16 per stage
            int cb = s * 2 + achk;       // 16B chunk index
            uint32_t aF[2][4], b1F[4][2], b3F[4][2];
#pragma unroll
            for (int mt = 0; mt < 2; mt++) {
                int row = wm * 32 + mt * 16 + arow;
                LDSM4(aF[mt], sA + row * 128 + ((cb ^ (row & 7)) << 4));
            }
#pragma unroll
            for (int pr = 0; pr < 2; pr++) {
                int row = wn * 32 + pr * 16 + arow;
                uint32_t off = row * 128 + ((cb ^ (row & 7)) << 4);
                uint32_t t1[4], t3[4];
                LDSM4(t1, sB1 + off);
                LDSM4(t3, sB3 + off);
                b1F[pr*2+0][0] = t1[0]; b1F[pr*2+0][1] = t1[2];
                b1F[pr*2+1][0] = t1[1]; b1F[pr*2+1][1] = t1[3];
                b3F[pr*2+0][0] = t3[0]; b3F[pr*2+0][1] = t3[2];
                b3F[pr*2+1][0] = t3[1]; b3F[pr*2+1][1] = t3[3];
            }
#pragma unroll
            for (int mt = 0; mt < 2; mt++)
#pragma unroll
                for (int nt = 0; nt < 4; nt++) {
                    MMA_F16(acc1[mt][nt], aF[mt], b1F[nt]);
                    MMA_F16(acc3[mt][nt], aF[mt], b3F[nt]);
                }
        }
        __syncthreads();
    }
    CP_WAIT0();

    // epilogue: h = fp16(silu(z1)*z3) -> g_H
#pragma unroll
    for (int mt = 0; mt < 2; mt++) {
#pragma unroll
        for (int half = 0; half < 2; half++) {
            int r = row0 + wm * 32 + mt * 16 + half * 8 + gid;
            if (r >= n_e) continue;
            __half* hrow = g_H + (size_t)(base + r) * HID + col0;
#pragma unroll
            for (int nt = 0; nt < 4; nt++) {
                float z1a = acc1[mt][nt][half*2+0], z1b = acc1[mt][nt][half*2+1];
                float z3a = acc3[mt][nt][half*2+0], z3b = acc3[mt][nt][half*2+1];
                float ha = z1a / (1.f + __expf(-z1a)) * z3a;
                float hb = z1b / (1.f + __expf(-z1b)) * z3b;
                *(__half2*)(hrow + wn * 32 + nt * 8 + ctid * 2) =
                    __floats2half2_rn(ha, hb);
            }
        }
    }
}

// ================= GEMM2: out[tok] += w * (H @ W2), mma.sync fp16 =================
// CTA 128m x 64n, BK=64. K = HID = 2048.
#define G2_STAGE 24576      // A 16K + B 8K
#define G2_SMEM  (3*G2_STAGE)

__global__ __launch_bounds__(256) void k_mma2(float* __restrict__ out) {
    extern __shared__ char smem[];
    int e    = blockIdx.y >> 5;
    int rt   = blockIdx.y & 31;
    int n_e  = g_counts[e];
    int row0 = rt * 128;
    if (row0 >= n_e) return;
    int base = g_offsets[e];
    int col0 = blockIdx.x * 64;

    uint32_t sb = smem_u32(smem);
    int tid = threadIdx.x, wid = tid >> 5, lane = tid & 31;
    int wm = wid >> 1, wn = wid & 1;
    int gid = lane >> 2, ctid = lane & 3;

    const __half* Bg = g_W2T + (size_t)e * DIM * HID + (size_t)col0 * HID;

    float acc[2][4][4] = {};
    const int KT = HID / 64;

    auto prefetch = [&](int buf, int kt) {
        int k0 = kt * 64;
        uint32_t sA = sb + buf * G2_STAGE;
        uint32_t sB = sA + 16384;
#pragma unroll
        for (int i = 0; i < 4; i++) {
            int task = tid + 256 * i;
            int r = task >> 3, c = task & 7;
            int rr = row0 + r;
            bool ok = (rr < n_e);
            const __half* src = g_H + (size_t)(base + (ok ? rr : 0)) * HID + k0 + c * 8;
            cpa16(sA + r * 128 + ((c ^ (r & 7)) << 4), src, ok ? 16 : 0);
        }
        {
            int task = tid;
            int r = task >> 2, c2 = task & 3;   // 64 rows x 4 tasks of 2 chunks
#pragma unroll
            for (int cc = 0; cc < 2; cc++) {
                int c = c2 * 2 + cc;
                cpa16(sB + r * 128 + ((c ^ (r & 7)) << 4),
                      Bg + (size_t)r * HID + k0 + c * 8, 16);
            }
        }
    };

    prefetch(0, 0); CP_COMMIT();
    prefetch(1, 1); CP_COMMIT();

    for (int kt = 0; kt < KT; kt++) {
        CP_WAIT1();
        __syncthreads();
        if (kt + 2 < KT) prefetch((kt + 2) % 3, kt + 2);
        CP_COMMIT();

        uint32_t sA = sb + (kt % 3) * G2_STAGE;
        uint32_t sB = sA + 16384;
        int arow = (lane & 15);
        int achk = (lane >> 4);
#pragma unroll
        for (int s = 0; s < 4; s++) {
            int cb = s * 2 + achk;
            uint32_t aF[2][4], bF[4][2];
#pragma unroll
            for (int mt = 0; mt < 2; mt++) {
                int row = wm * 32 + mt * 16 + arow;
                LDSM4(aF[mt], sA + row * 128 + ((cb ^ (row & 7)) << 4));
            }
#pragma unroll
            for (int pr = 0; pr < 2; pr++) {
                int row = wn * 32 + pr * 16 + arow;
                uint32_t t[4];
                LDSM4(t, sB + row * 128 + ((cb ^ (row & 7)) << 4));
                bF[pr*2+0][0] = t[0]; bF[pr*2+0][1] = t[2];
                bF[pr*2+1][0] = t[1]; bF[pr*2+1][1] = t[3];
            }
#pragma unroll
            for (int mt = 0; mt < 2; mt++)
#pragma unroll
                for (int nt = 0; nt < 4; nt++)
                    MMA_F16(acc[mt][nt], aF[mt], bF[nt]);
        }
        __syncthreads();
    }
    CP_WAIT0();

    // epilogue: out[tok] += w * acc
#pragma unroll
    for (int mt = 0; mt < 2; mt++) {
#pragma unroll
        for (int half = 0; half < 2; half++) {
            int r = row0 + wm * 32 + mt * 16 + half * 8 + gid;
            if (r >= n_e) continue;
            float w  = g_slot_w[base + r];
            int  tok = g_slot_tok[base + r];
            float* orow = out + (size_t)tok * DIM + col0;
#pragma unroll
            for (int nt = 0; nt < 4; nt++) {
                int c = wn * 32 + nt * 8 + ctid * 2;
                atomicAdd(&orow[c],     w * acc[mt][nt][half*2+0]);
                atomicAdd(&orow[c + 1], w * acc[mt][nt][half*2+1]);
            }
        }
    }
}

// ---------------- launch ----------------
extern "C" void kernel_launch(void* const* d_in, const int* in_sizes, int n_in,
                              void* d_out, int out_size)
{
    const float* x  = (const float*)d_in[0];
    const float* Wg = (const float*)d_in[1];
    const float* W1 = (const float*)d_in[2];
    const float* W3 = (const float*)d_in[3];
    const float* W2 = (const float*)d_in[4];
    float* out = (float*)d_out;
    int T = in_sizes[0] / DIM;

    cudaFuncSetAttribute(k_mma1, cudaFuncAttributeMaxDynamicSharedMemorySize, G1_SMEM);
    cudaFuncSetAttribute(k_mma2, cudaFuncAttributeMaxDynamicSharedMemorySize, G2_SMEM);

    k_init<<<(out_size + 255) / 256, 256>>>(out, out_size);
    k_cvt_x<<<(T * DIM + 255) / 256, 256>>>(x, T * DIM);

    k_transpose<<<dim3(HID/32, DIM/32, NE), dim3(32, 8)>>>(W1, 0, DIM, HID);
    k_transpose<<<dim3(HID/32, DIM/32, NE), dim3(32, 8)>>>(W3, 1, DIM, HID);
    k_transpose<<<dim3(DIM/32, HID/32, NE), dim3(32, 8)>>>(W2, 2, HID, DIM);

    k_route<<<(T + 3) / 4, 128>>>(x, Wg, T);
    k_offsets<<<1, 1>>>();
    k_scatter<<<(T + 255) / 256, 256>>>(T);

    k_mma1<<<dim3(HID/64, NE * (MAXT/128)), 256, G1_SMEM>>>();
    k_mma2<<<dim3(DIM/64, NE * (MAXT/128)), 256, G2_SMEM>>>(out);
}

// round 5
// speedup vs baseline: 5.5131x; 1.1585x over previous
#include <cuda_runtime.h>
#include <cuda_fp16.h>
#include <math.h>
#include <stdint.h>

#define DIM  1024
#define HID  2048
#define NE   8
#define MAXT 4096
#define MAXSLOTS (MAXT*2)

// ---------------- device scratch ----------------
__device__ int    g_counts[NE];
__device__ int    g_offsets[NE+1];
__device__ int    g_fill[NE];
__device__ int    g_tok_e[MAXT*2];
__device__ float  g_tok_w[MAXT*2];
__device__ int    g_slot_tok[MAXSLOTS];
__device__ float  g_slot_w[MAXSLOTS];
__device__ __half g_Xh[(size_t)MAXT*DIM];
__device__ __half g_H[(size_t)MAXSLOTS*HID];
__device__ __half g_W1T[(size_t)NE*HID*DIM];    // [E][HID][DIM] k-major
__device__ __half g_W3T[(size_t)NE*HID*DIM];
__device__ __half g_W2T[(size_t)NE*DIM*HID];    // [E][DIM][HID] k-major

// ---------------- helpers ----------------
__device__ __forceinline__ uint32_t smem_u32(const void* p) {
    uint32_t a;
    asm("{ .reg .u64 t; cvta.to.shared.u64 t, %1; cvt.u32.u64 %0, t; }" : "=r"(a) : "l"(p));
    return a;
}
__device__ __forceinline__ void cpa16(uint32_t dst, const void* src, int sz) {
    asm volatile("cp.async.cg.shared.global [%0], [%1], 16, %2;"
                 :: "r"(dst), "l"(src), "r"(sz) : "memory");
}
#define CP_COMMIT() asm volatile("cp.async.commit_group;" ::: "memory")
#define CP_WAIT1()  asm volatile("cp.async.wait_group 1;" ::: "memory")
#define CP_WAIT0()  asm volatile("cp.async.wait_group 0;" ::: "memory")

#define LDSM4(r, addr) \
    asm volatile("ldmatrix.sync.aligned.m8n8.x4.shared.b16 {%0,%1,%2,%3}, [%4];" \
        : "=r"((r)[0]), "=r"((r)[1]), "=r"((r)[2]), "=r"((r)[3]) : "r"(addr))

#define MMA_F16(d, a, b) \
    asm volatile("mma.sync.aligned.m16n8k16.row.col.f32.f16.f16.f32 " \
        "{%0,%1,%2,%3}, {%4,%5,%6,%7}, {%8,%9}, {%0,%1,%2,%3};" \
        : "+f"((d)[0]), "+f"((d)[1]), "+f"((d)[2]), "+f"((d)[3]) \
        : "r"((a)[0]), "r"((a)[1]), "r"((a)[2]), "r"((a)[3]), \
          "r"((b)[0]), "r"((b)[1]))

// ---------------- init ----------------
__global__ void k_init(float* out, int outN) {
    int i = blockIdx.x * blockDim.x + threadIdx.x;
    if (i < outN) out[i] = 0.f;
    if (i < NE) { g_counts[i] = 0; g_fill[i] = 0; }
}

__global__ void k_cvt_x(const float* __restrict__ x, int n2) {
    int i = blockIdx.x * blockDim.x + threadIdx.x;   // i indexes float2
    if (i < n2) {
        float2 v = ((const float2*)x)[i];
        ((__half2*)g_Xh)[i] = __floats2half2_rn(v.x, v.y);
    }
}

// ---------------- transpose + fp16 convert: 64x64 tiles, vectorized ----------------
__global__ __launch_bounds__(256) void k_transpose(const float* __restrict__ in, int sel, int R, int C) {
    __shared__ float tile[64][65];
    __half* out = (sel == 0) ? g_W1T : (sel == 1) ? g_W3T : g_W2T;
    int e = blockIdx.z;
    const float* inp = in + (size_t)e * R * C;
    __half* outp = out + (size_t)e * R * C;
    int x0 = blockIdx.x * 64;       // C coord
    int y0 = blockIdx.y * 64;       // R coord
    int tid = threadIdx.x;

    // read: 64 rows x 16 float4 = 1024 tasks, 4/thread
#pragma unroll
    for (int i = 0; i < 4; i++) {
        int task = tid + 256 * i;
        int r = task >> 4, c4 = task & 15;
        float4 v = *(const float4*)(inp + (size_t)(y0 + r) * C + x0 + c4 * 4);
        tile[r][c4*4+0] = v.x; tile[r][c4*4+1] = v.y;
        tile[r][c4*4+2] = v.z; tile[r][c4*4+3] = v.w;
    }
    __syncthreads();

    // write transposed as halves: 64 out-rows x 8 uint4(8 halves) = 512 tasks, 2/thread
#pragma unroll
    for (int i = 0; i < 2; i++) {
        int task = tid + 256 * i;
        int rr = task >> 3, c8 = task & 7;
        __align__(16) __half h[8];
#pragma unroll
        for (int j = 0; j < 8; j++)
            h[j] = __float2half(tile[c8*8+j][rr]);
        *(uint4*)(outp + (size_t)(x0 + rr) * R + y0 + c8 * 8) = *(uint4*)h;
    }
}

// ---------------- routing (fp32) ----------------
__global__ void k_route(const float* __restrict__ x, const float* __restrict__ Wg, int T) {
    int warp = (blockIdx.x * blockDim.x + threadIdx.x) >> 5;
    int lane = threadIdx.x & 31;
    if (warp >= T) return;
    const float* xr = x + (size_t)warp * DIM;
    float acc[NE];
#pragma unroll
    for (int e = 0; e < NE; e++) acc[e] = 0.f;
    for (int i = lane; i < DIM; i += 32) {
        float xv = xr[i];
        const float* wg = Wg + (size_t)i * NE;
#pragma unroll
        for (int e = 0; e < NE; e++) acc[e] += xv * wg[e];
    }
#pragma unroll
    for (int off = 16; off > 0; off >>= 1)
#pragma unroll
        for (int e = 0; e < NE; e++)
            acc[e] += __shfl_down_sync(0xffffffffu, acc[e], off);
    if (lane == 0) {
        int i0 = 0; float s0 = acc[0];
#pragma unroll
        for (int e = 1; e < NE; e++) if (acc[e] > s0) { s0 = acc[e]; i0 = e; }
        int i1 = -1; float s1 = -1e30f;
#pragma unroll
        for (int e = 0; e < NE; e++) if (e != i0 && acc[e] > s1) { s1 = acc[e]; i1 = e; }
        float e1 = expf(s1 - s0);
        float inv = 1.f / (1.f + e1);
        g_tok_e[warp*2+0] = i0;  g_tok_w[warp*2+0] = inv;
        g_tok_e[warp*2+1] = i1;  g_tok_w[warp*2+1] = e1 * inv;
        atomicAdd(&g_counts[i0], 1);
        atomicAdd(&g_counts[i1], 1);
    }
}

__global__ void k_offsets() {
    int s = 0; g_offsets[0] = 0;
#pragma unroll
    for (int e = 0; e < NE; e++) { s += g_counts[e]; g_offsets[e+1] = s; }
}

__global__ void k_scatter(int T) {
    int t = blockIdx.x * blockDim.x + threadIdx.x;
    if (t >= T) return;
#pragma unroll
    for (int k = 0; k < 2; k++) {
        int e = g_tok_e[t*2+k];
        int pos = atomicAdd(&g_fill[e], 1);
        int slot = g_offsets[e] + pos;
        g_slot_tok[slot] = t;
        g_slot_w[slot]   = g_tok_w[t*2+k];
    }
}

// ================= GEMM1: H = silu(Xg@W1) * (Xg@W3), mma.sync fp16 =================
// CTA 128m x 64n (both W1,W3), BK=64, 3-stage. 8 warps 4x2, warp 32x32 per matrix.
#define G1_STAGE 32768      // A 16K + B1 8K + B3 8K
#define G1_SMEM  (3*G1_STAGE + 512)

__global__ __launch_bounds__(256) void k_mma1() {
    extern __shared__ char smem[];
    int e    = blockIdx.y >> 5;
    int rt   = blockIdx.y & 31;
    int n_e  = g_counts[e];
    int row0 = rt * 128;
    if (row0 >= n_e) return;
    int base = g_offsets[e];
    int col0 = blockIdx.x * 64;

    uint32_t sb = smem_u32(smem);
    int tid = threadIdx.x, wid = tid >> 5, lane = tid & 31;
    int wm = wid >> 1, wn = wid & 1;
    int gid = lane >> 2, ctid = lane & 3;
    int* toks = (int*)(smem + 3*G1_STAGE);

    if (tid < 128) {
        int r = row0 + tid;
        toks[tid] = (r < n_e) ? g_slot_tok[base + r] : -1;
    }
    __syncthreads();

    const __half* B1g = g_W1T + (size_t)e * HID * DIM + (size_t)col0 * DIM;
    const __half* B3g = g_W3T + (size_t)e * HID * DIM + (size_t)col0 * DIM;

    float acc1[2][4][4] = {}, acc3[2][4][4] = {};
    const int KT = DIM / 64;

    auto prefetch = [&](int buf, int kt) {
        int k0 = kt * 64;
        uint32_t sA  = sb + buf * G1_STAGE;
        uint32_t sB1 = sA + 16384;
        uint32_t sB3 = sA + 24576;
#pragma unroll
        for (int i = 0; i < 4; i++) {
            int task = tid + 256 * i;
            int r = task >> 3, c = task & 7;
            int tok = toks[r];
            const __half* src = g_Xh + (size_t)(tok < 0 ? 0 : tok) * DIM + k0 + c * 8;
            cpa16(sA + r * 128 + ((c ^ (r & 7)) << 4), src, tok < 0 ? 0 : 16);
        }
#pragma unroll
        for (int i = 0; i < 2; i++) {
            int task = tid + 256 * i;
            int r = task >> 3, c = task & 7;
            uint32_t off = r * 128 + ((c ^ (r & 7)) << 4);
            cpa16(sB1 + off, B1g + (size_t)r * DIM + k0 + c * 8, 16);
            cpa16(sB3 + off, B3g + (size_t)r * DIM + k0 + c * 8, 16);
        }
    };

    prefetch(0, 0); CP_COMMIT();
    prefetch(1, 1); CP_COMMIT();

    for (int kt = 0; kt < KT; kt++) {
        CP_WAIT1();
        __syncthreads();
        if (kt + 2 < KT) prefetch((kt + 2) % 3, kt + 2);
        CP_COMMIT();

        uint32_t sA  = sb + (kt % 3) * G1_STAGE;
        uint32_t sB1 = sA + 16384;
        uint32_t sB3 = sA + 24576;
        int arow = (lane & 15);
        int achk = (lane >> 4);
#pragma unroll
        for (int s = 0; s < 4; s++) {
            int cb = s * 2 + achk;
            uint32_t aF[2][4], b1F[4][2], b3F[4][2];
#pragma unroll
            for (int mt = 0; mt < 2; mt++) {
                int row = wm * 32 + mt * 16 + arow;
                LDSM4(aF[mt], sA + row * 128 + ((cb ^ (row & 7)) << 4));
            }
#pragma unroll
            for (int pr = 0; pr < 2; pr++) {
                int row = wn * 32 + pr * 16 + arow;
                uint32_t off = row * 128 + ((cb ^ (row & 7)) << 4);
                uint32_t t1[4], t3[4];
                LDSM4(t1, sB1 + off);
                LDSM4(t3, sB3 + off);
                b1F[pr*2+0][0] = t1[0]; b1F[pr*2+0][1] = t1[2];
                b1F[pr*2+1][0] = t1[1]; b1F[pr*2+1][1] = t1[3];
                b3F[pr*2+0][0] = t3[0]; b3F[pr*2+0][1] = t3[2];
                b3F[pr*2+1][0] = t3[1]; b3F[pr*2+1][1] = t3[3];
            }
#pragma unroll
            for (int mt = 0; mt < 2; mt++)
#pragma unroll
                for (int nt = 0; nt < 4; nt++) {
                    MMA_F16(acc1[mt][nt], aF[mt], b1F[nt]);
                    MMA_F16(acc3[mt][nt], aF[mt], b3F[nt]);
                }
        }
        __syncthreads();
    }
    CP_WAIT0();

#pragma unroll
    for (int mt = 0; mt < 2; mt++) {
#pragma unroll
        for (int half = 0; half < 2; half++) {
            int r = row0 + wm * 32 + mt * 16 + half * 8 + gid;
            if (r >= n_e) continue;
            __half* hrow = g_H + (size_t)(base + r) * HID + col0;
#pragma unroll
            for (int nt = 0; nt < 4; nt++) {
                float z1a = acc1[mt][nt][half*2+0], z1b = acc1[mt][nt][half*2+1];
                float z3a = acc3[mt][nt][half*2+0], z3b = acc3[mt][nt][half*2+1];
                float ha = z1a / (1.f + __expf(-z1a)) * z3a;
                float hb = z1b / (1.f + __expf(-z1b)) * z3b;
                *(__half2*)(hrow + wn * 32 + nt * 8 + ctid * 2) =
                    __floats2half2_rn(ha, hb);
            }
        }
    }
}

// ================= GEMM2: out[tok] += w * (H @ W2), mma.sync fp16 =================
// CTA 128m x 128n, BK=64, 3-stage. 8 warps 4x2, warp tile 32x64.
#define G2_STAGE 32768      // A 16K + B 16K
#define G2_SMEM  (3*G2_STAGE)

__global__ __launch_bounds__(256) void k_mma2(float* __restrict__ out) {
    extern __shared__ char smem[];
    int e    = blockIdx.y >> 5;
    int rt   = blockIdx.y & 31;
    int n_e  = g_counts[e];
    int row0 = rt * 128;
    if (row0 >= n_e) return;
    int base = g_offsets[e];
    int col0 = blockIdx.x * 128;

    uint32_t sb = smem_u32(smem);
    int tid = threadIdx.x, wid = tid >> 5, lane = tid & 31;
    int wm = wid >> 1, wn = wid & 1;
    int gid = lane >> 2, ctid = lane & 3;

    const __half* Bg = g_W2T + (size_t)e * DIM * HID + (size_t)col0 * HID;

    float acc[2][8][4] = {};
    const int KT = HID / 64;

    auto prefetch = [&](int buf, int kt) {
        int k0 = kt * 64;
        uint32_t sA = sb + buf * G2_STAGE;
        uint32_t sB = sA + 16384;
#pragma unroll
        for (int i = 0; i < 4; i++) {      // A: 128 rows x 8 chunks
            int task = tid + 256 * i;
            int r = task >> 3, c = task & 7;
            int rr = row0 + r;
            bool ok = (rr < n_e);
            const __half* src = g_H + (size_t)(base + (ok ? rr : 0)) * HID + k0 + c * 8;
            cpa16(sA + r * 128 + ((c ^ (r & 7)) << 4), src, ok ? 16 : 0);
        }
#pragma unroll
        for (int i = 0; i < 4; i++) {      // B: 128 n-rows x 8 chunks
            int task = tid + 256 * i;
            int r = task >> 3, c = task & 7;
            cpa16(sB + r * 128 + ((c ^ (r & 7)) << 4),
                  Bg + (size_t)r * HID + k0 + c * 8, 16);
        }
    };

    prefetch(0, 0); CP_COMMIT();
    prefetch(1, 1); CP_COMMIT();

    for (int kt = 0; kt < KT; kt++) {
        CP_WAIT1();
        __syncthreads();
        if (kt + 2 < KT) prefetch((kt + 2) % 3, kt + 2);
        CP_COMMIT();

        uint32_t sA = sb + (kt % 3) * G2_STAGE;
        uint32_t sB = sA + 16384;
        int arow = (lane & 15);
        int achk = (lane >> 4);
#pragma unroll
        for (int s = 0; s < 4; s++) {
            int cb = s * 2 + achk;
            uint32_t aF[2][4], bF[8][2];
#pragma unroll
            for (int mt = 0; mt < 2; mt++) {
                int row = wm * 32 + mt * 16 + arow;
                LDSM4(aF[mt], sA + row * 128 + ((cb ^ (row & 7)) << 4));
            }
#pragma unroll
            for (int pr = 0; pr < 4; pr++) {
                int row = wn * 64 + pr * 16 + arow;
                uint32_t t[4];
                LDSM4(t, sB + row * 128 + ((cb ^ (row & 7)) << 4));
                bF[pr*2+0][0] = t[0]; bF[pr*2+0][1] = t[2];
                bF[pr*2+1][0] = t[1]; bF[pr*2+1][1] = t[3];
            }
#pragma unroll
            for (int mt = 0; mt < 2; mt++)
#pragma unroll
                for (int nt = 0; nt < 8; nt++)
                    MMA_F16(acc[mt][nt], aF[mt], bF[nt]);
        }
        __syncthreads();
    }
    CP_WAIT0();

#pragma unroll
    for (int mt = 0; mt < 2; mt++) {
#pragma unroll
        for (int half = 0; half < 2; half++) {
            int r = row0 + wm * 32 + mt * 16 + half * 8 + gid;
            if (r >= n_e) continue;
            float w  = g_slot_w[base + r];
            int  tok = g_slot_tok[base + r];
            float* orow = out + (size_t)tok * DIM + col0;
#pragma unroll
            for (int nt = 0; nt < 8; nt++) {
                int c = wn * 64 + nt * 8 + ctid * 2;
                atomicAdd(&orow[c],     w * acc[mt][nt][half*2+0]);
                atomicAdd(&orow[c + 1], w * acc[mt][nt][half*2+1]);
            }
        }
    }
}

// ---------------- launch ----------------
extern "C" void kernel_launch(void* const* d_in, const int* in_sizes, int n_in,
                              void* d_out, int out_size)
{
    const float* x  = (const float*)d_in[0];
    const float* Wg = (const float*)d_in[1];
    const float* W1 = (const float*)d_in[2];
    const float* W3 = (const float*)d_in[3];
    const float* W2 = (const float*)d_in[4];
    float* out = (float*)d_out;
    int T = in_sizes[0] / DIM;

    cudaFuncSetAttribute(k_mma1, cudaFuncAttributeMaxDynamicSharedMemorySize, G1_SMEM);
    cudaFuncSetAttribute(k_mma2, cudaFuncAttributeMaxDynamicSharedMemorySize, G2_SMEM);

    k_init<<<(out_size + 255) / 256, 256>>>(out, out_size);
    k_cvt_x<<<(T * DIM / 2 + 255) / 256, 256>>>(x, T * DIM / 2);

    k_transpose<<<dim3(HID/64, DIM/64, NE), 256>>>(W1, 0, DIM, HID);
    k_transpose<<<dim3(HID/64, DIM/64, NE), 256>>>(W3, 1, DIM, HID);
    k_transpose<<<dim3(DIM/64, HID/64, NE), 256>>>(W2, 2, HID, DIM);

    k_route<<<(T + 3) / 4, 128>>>(x, Wg, T);
    k_offsets<<<1, 1>>>();
    k_scatter<<<(T + 255) / 256, 256>>>(T);

    k_mma1<<<dim3(HID/64, NE * (MAXT/128)), 256, G1_SMEM>>>();
    k_mma2<<<dim3(DIM/128, NE * (MAXT/128)), 256, G2_SMEM>>>(out);
}

// round 7
// speedup vs baseline: 5.7065x; 1.0351x over previous
#include <cuda_runtime.h>
#include <cuda_fp16.h>
#include <math.h>
#include <stdint.h>

#define DIM  1024
#define HID  2048
#define NE   8
#define MAXT 4096
#define MAXSLOTS (MAXT*2)

// ---------------- device scratch ----------------
__device__ int    g_counts[NE];
__device__ int    g_fill[NE];
__device__ int    g_tok_e[MAXT*2];
__device__ float  g_tok_w[MAXT*2];
__device__ int    g_slot_tok[MAXSLOTS];
__device__ float  g_slot_w[MAXSLOTS];
__device__ __half g_Xh[(size_t)MAXT*DIM];
__device__ __half g_H[(size_t)MAXSLOTS*HID];
__device__ __half g_W1T[(size_t)NE*HID*DIM];    // [E][HID][DIM] k-major
__device__ __half g_W3T[(size_t)NE*HID*DIM];
__device__ __half g_W2T[(size_t)NE*DIM*HID];    // [E][DIM][HID] k-major

// ---------------- helpers ----------------
__device__ __forceinline__ uint32_t smem_u32(const void* p) {
    uint32_t a;
    asm("{ .reg .u64 t; cvta.to.shared.u64 t, %1; cvt.u32.u64 %0, t; }" : "=r"(a) : "l"(p));
    return a;
}
__device__ __forceinline__ void cpa16(uint32_t dst, const void* src, int sz) {
    asm volatile("cp.async.cg.shared.global [%0], [%1], 16, %2;"
                 :: "r"(dst), "l"(src), "r"(sz) : "memory");
}
#define CP_COMMIT() asm volatile("cp.async.commit_group;" ::: "memory")
#define CP_WAIT1()  asm volatile("cp.async.wait_group 1;" ::: "memory")
#define CP_WAIT0()  asm volatile("cp.async.wait_group 0;" ::: "memory")

#define LDSM4(r, addr) \
    asm volatile("ldmatrix.sync.aligned.m8n8.x4.shared.b16 {%0,%1,%2,%3}, [%4];" \
        : "=r"((r)[0]), "=r"((r)[1]), "=r"((r)[2]), "=r"((r)[3]) : "r"(addr))

#define MMA_F16(d, a, b) \
    asm volatile("mma.sync.aligned.m16n8k16.row.col.f32.f16.f16.f32 " \
        "{%0,%1,%2,%3}, {%4,%5,%6,%7}, {%8,%9}, {%0,%1,%2,%3};" \
        : "+f"((d)[0]), "+f"((d)[1]), "+f"((d)[2]), "+f"((d)[3]) \
        : "r"((a)[0]), "r"((a)[1]), "r"((a)[2]), "r"((a)[3]), \
          "r"((b)[0]), "r"((b)[1]))

__device__ __forceinline__ int expert_base(int e) {
    int b = 0;
#pragma unroll
    for (int i = 0; i < NE; i++) b += (i < e) ? g_counts[i] : 0;
    return b;
}

// ---------------- fused front: zero out, cvt x->fp16, route ----------------
// (counters are zeroed ONLY in k_zero_cnt, which runs strictly before this grid)
__global__ __launch_bounds__(256) void k_front(
    const float* __restrict__ x, const float* __restrict__ Wg,
    float* __restrict__ out, int T)
{
    int b = blockIdx.x;
    if (b < 512) {
        // ---- routing: warp per token, 8 warps/block ----
        int warp = (b * 256 + threadIdx.x) >> 5;
        int lane = threadIdx.x & 31;
        if (warp >= T) return;
        const float* xr = x + (size_t)warp * DIM;
        float acc[NE];
#pragma unroll
        for (int e = 0; e < NE; e++) acc[e] = 0.f;
        for (int i = lane; i < DIM; i += 32) {
            float xv = xr[i];
            const float* wg = Wg + (size_t)i * NE;
#pragma unroll
            for (int e = 0; e < NE; e++) acc[e] += xv * wg[e];
        }
#pragma unroll
        for (int off = 16; off > 0; off >>= 1)
#pragma unroll
            for (int e = 0; e < NE; e++)
                acc[e] += __shfl_down_sync(0xffffffffu, acc[e], off);
        if (lane == 0) {
            int i0 = 0; float s0 = acc[0];
#pragma unroll
            for (int e = 1; e < NE; e++) if (acc[e] > s0) { s0 = acc[e]; i0 = e; }
            int i1 = -1; float s1 = -1e30f;
#pragma unroll
            for (int e = 0; e < NE; e++) if (e != i0 && acc[e] > s1) { s1 = acc[e]; i1 = e; }
            float e1 = expf(s1 - s0);
            float inv = 1.f / (1.f + e1);
            g_tok_e[warp*2+0] = i0;  g_tok_w[warp*2+0] = inv;
            g_tok_e[warp*2+1] = i1;  g_tok_w[warp*2+1] = e1 * inv;
            atomicAdd(&g_counts[i0], 1);
            atomicAdd(&g_counts[i1], 1);
        }
    } else if (b < 1024) {
        // ---- cvt x -> fp16: 8 floats per op ----
        int idx = (b - 512) * 256 + threadIdx.x;   // 131072 threads
        int n8 = T * DIM / 8;
        for (int i = idx; i < n8; i += 131072) {
            float4 v0 = ((const float4*)x)[i*2+0];
            float4 v1 = ((const float4*)x)[i*2+1];
            __align__(16) __half h[8];
            h[0]=__float2half(v0.x); h[1]=__float2half(v0.y);
            h[2]=__float2half(v0.z); h[3]=__float2half(v0.w);
            h[4]=__float2half(v1.x); h[5]=__float2half(v1.y);
            h[6]=__float2half(v1.z); h[7]=__float2half(v1.w);
            ((uint4*)g_Xh)[i] = *(uint4*)h;
        }
    } else {
        // ---- zero out ----
        int idx = (b - 1024) * 256 + threadIdx.x;
        int n4 = T * DIM / 4;
        uint4 z = make_uint4(0,0,0,0);
        for (int i = idx; i < n4; i += 131072)
            ((uint4*)out)[i] = z;
    }
}

// counters zeroed strictly before k_front (separate launch => ordered)
__global__ void k_zero_cnt() {
    if (threadIdx.x < NE) { g_counts[threadIdx.x] = 0; g_fill[threadIdx.x] = 0; }
}

// ---------------- fused transpose + fp16 convert (all 3 weights) ----------------
__global__ __launch_bounds__(256) void k_transpose_all(
    const float* __restrict__ W1, const float* __restrict__ W3,
    const float* __restrict__ W2)
{
    __shared__ float tile[64][65];
    int bid = blockIdx.x;
    int sel = bid >> 12;             // 4096 tiles per matrix
    int t   = bid & 4095;
    const float* in; __half* out; int R, C, tx, ty;
    if (sel < 2) {
        R = DIM; C = HID;
        int e = t >> 9; int tt = t & 511;
        tx = tt & 31; ty = tt >> 5;
        in  = (sel == 0 ? W1 : W3) + (size_t)e * R * C;
        out = (sel == 0 ? g_W1T : g_W3T) + (size_t)e * R * C;
    } else {
        R = HID; C = DIM;
        int e = t >> 9; int tt = t & 511;
        tx = tt & 15; ty = tt >> 4;
        in  = W2 + (size_t)e * R * C;
        out = g_W2T + (size_t)e * R * C;
    }
    int x0 = tx * 64, y0 = ty * 64;
    int tid = threadIdx.x;

#pragma unroll
    for (int i = 0; i < 4; i++) {
        int task = tid + 256 * i;
        int r = task >> 4, c4 = task & 15;
        float4 v = *(const float4*)(in + (size_t)(y0 + r) * C + x0 + c4 * 4);
        tile[r][c4*4+0] = v.x; tile[r][c4*4+1] = v.y;
        tile[r][c4*4+2] = v.z; tile[r][c4*4+3] = v.w;
    }
    __syncthreads();
#pragma unroll
    for (int i = 0; i < 2; i++) {
        int task = tid + 256 * i;
        int rr = task >> 3, c8 = task & 7;
        __align__(16) __half h[8];
#pragma unroll
        for (int j = 0; j < 8; j++)
            h[j] = __float2half(tile[c8*8+j][rr]);
        *(uint4*)(out + (size_t)(x0 + rr) * R + y0 + c8 * 8) = *(uint4*)h;
    }
}

// ---------------- scatter (offsets computed inline) ----------------
__global__ void k_scatter(int T) {
    int t = blockIdx.x * blockDim.x + threadIdx.x;
    if (t >= T) return;
#pragma unroll
    for (int k = 0; k < 2; k++) {
        int e = g_tok_e[t*2+k];
        int pos = atomicAdd(&g_fill[e], 1);
        int slot = expert_base(e) + pos;
        g_slot_tok[slot] = t;
        g_slot_w[slot]   = g_tok_w[t*2+k];
    }
}

// ================= GEMM1: H = silu(Xg@W1) * (Xg@W3) =================
#define G1_STAGE 32768
#define G1_SMEM  (3*G1_STAGE + 512)

__global__ __launch_bounds__(256) void k_mma1() {
    extern __shared__ char smem[];
    int e    = blockIdx.y >> 5;
    int rt   = blockIdx.y & 31;
    int n_e  = g_counts[e];
    int row0 = rt * 128;
    if (row0 >= n_e) return;
    int base = expert_base(e);
    int col0 = blockIdx.x * 64;

    uint32_t sb = smem_u32(smem);
    int tid = threadIdx.x, wid = tid >> 5, lane = tid & 31;
    int wm = wid >> 1, wn = wid & 1;
    int gid = lane >> 2, ctid = lane & 3;
    int* toks = (int*)(smem + 3*G1_STAGE);

    if (tid < 128) {
        int r = row0 + tid;
        toks[tid] = (r < n_e) ? g_slot_tok[base + r] : -1;
    }
    __syncthreads();

    const __half* B1g = g_W1T + (size_t)e * HID * DIM + (size_t)col0 * DIM;
    const __half* B3g = g_W3T + (size_t)e * HID * DIM + (size_t)col0 * DIM;

    float acc1[2][4][4] = {}, acc3[2][4][4] = {};
    const int KT = DIM / 64;

    auto prefetch = [&](int buf, int kt) {
        int k0 = kt * 64;
        uint32_t sA  = sb + buf * G1_STAGE;
        uint32_t sB1 = sA + 16384;
        uint32_t sB3 = sA + 24576;
#pragma unroll
        for (int i = 0; i < 4; i++) {
            int task = tid + 256 * i;
            int r = task >> 3, c = task & 7;
            int tok = toks[r];
            const __half* src = g_Xh + (size_t)(tok < 0 ? 0 : tok) * DIM + k0 + c * 8;
            cpa16(sA + r * 128 + ((c ^ (r & 7)) << 4), src, tok < 0 ? 0 : 16);
        }
#pragma unroll
        for (int i = 0; i < 2; i++) {
            int task = tid + 256 * i;
            int r = task >> 3, c = task & 7;
            uint32_t off = r * 128 + ((c ^ (r & 7)) << 4);
            cpa16(sB1 + off, B1g + (size_t)r * DIM + k0 + c * 8, 16);
            cpa16(sB3 + off, B3g + (size_t)r * DIM + k0 + c * 8, 16);
        }
    };

    prefetch(0, 0); CP_COMMIT();
    prefetch(1, 1); CP_COMMIT();

    for (int kt = 0; kt < KT; kt++) {
        CP_WAIT1();
        __syncthreads();                 // single barrier per stage
        if (kt + 2 < KT) prefetch((kt + 2) % 3, kt + 2);
        CP_COMMIT();

        uint32_t sA  = sb + (kt % 3) * G1_STAGE;
        uint32_t sB1 = sA + 16384;
        uint32_t sB3 = sA + 24576;
        int arow = (lane & 15);
        int achk = (lane >> 4);
#pragma unroll
        for (int s = 0; s < 4; s++) {
            int cb = s * 2 + achk;
            uint32_t aF[2][4], b1F[4][2], b3F[4][2];
#pragma unroll
            for (int mt = 0; mt < 2; mt++) {
                int row = wm * 32 + mt * 16 + arow;
                LDSM4(aF[mt], sA + row * 128 + ((cb ^ (row & 7)) << 4));
            }
#pragma unroll
            for (int pr = 0; pr < 2; pr++) {
                int row = wn * 32 + pr * 16 + arow;
                uint32_t off = row * 128 + ((cb ^ (row & 7)) << 4);
                uint32_t t1[4], t3[4];
                LDSM4(t1, sB1 + off);
                LDSM4(t3, sB3 + off);
                b1F[pr*2+0][0] = t1[0]; b1F[pr*2+0][1] = t1[2];
                b1F[pr*2+1][0] = t1[1]; b1F[pr*2+1][1] = t1[3];
                b3F[pr*2+0][0] = t3[0]; b3F[pr*2+0][1] = t3[2];
                b3F[pr*2+1][0] = t3[1]; b3F[pr*2+1][1] = t3[3];
            }
#pragma unroll
            for (int mt = 0; mt < 2; mt++)
#pragma unroll
                for (int nt = 0; nt < 4; nt++) {
                    MMA_F16(acc1[mt][nt], aF[mt], b1F[nt]);
                    MMA_F16(acc3[mt][nt], aF[mt], b3F[nt]);
                }
        }
    }
    CP_WAIT0();

#pragma unroll
    for (int mt = 0; mt < 2; mt++) {
#pragma unroll
        for (int half = 0; half < 2; half++) {
            int r = row0 + wm * 32 + mt * 16 + half * 8 + gid;
            if (r >= n_e) continue;
            __half* hrow = g_H + (size_t)(base + r) * HID + col0;
#pragma unroll
            for (int nt = 0; nt < 4; nt++) {
                float z1a = acc1[mt][nt][half*2+0], z1b = acc1[mt][nt][half*2+1];
                float z3a = acc3[mt][nt][half*2+0], z3b = acc3[mt][nt][half*2+1];
                float ha = z1a / (1.f + __expf(-z1a)) * z3a;
                float hb = z1b / (1.f + __expf(-z1b)) * z3b;
                *(__half2*)(hrow + wn * 32 + nt * 8 + ctid * 2) =
                    __floats2half2_rn(ha, hb);
            }
        }
    }
}

// ================= GEMM2: out[tok] += w * (H @ W2) =================
#define G2_STAGE 32768
#define G2_SMEM  (3*G2_STAGE)

__global__ __launch_bounds__(256) void k_mma2(float* __restrict__ out) {
    extern __shared__ char smem[];
    int e    = blockIdx.y >> 5;
    int rt   = blockIdx.y & 31;
    int n_e  = g_counts[e];
    int row0 = rt * 128;
    if (row0 >= n_e) return;
    int base = expert_base(e);
    int col0 = blockIdx.x * 128;

    uint32_t sb = smem_u32(smem);
    int tid = threadIdx.x, wid = tid >> 5, lane = tid & 31;
    int wm = wid >> 1, wn = wid & 1;
    int gid = lane >> 2, ctid = lane & 3;

    const __half* Bg = g_W2T + (size_t)e * DIM * HID + (size_t)col0 * HID;

    float acc[2][8][4] = {};
    const int KT = HID / 64;

    auto prefetch = [&](int buf, int kt) {
        int k0 = kt * 64;
        uint32_t sA = sb + buf * G2_STAGE;
        uint32_t sB = sA + 16384;
#pragma unroll
        for (int i = 0; i < 4; i++) {
            int task = tid + 256 * i;
            int r = task >> 3, c = task & 7;
            int rr = row0 + r;
            bool ok = (rr < n_e);
            const __half* src = g_H + (size_t)(base + (ok ? rr : 0)) * HID + k0 + c * 8;
            cpa16(sA + r * 128 + ((c ^ (r & 7)) << 4), src, ok ? 16 : 0);
        }
#pragma unroll
        for (int i = 0; i < 4; i++) {
            int task = tid + 256 * i;
            int r = task >> 3, c = task & 7;
            cpa16(sB + r * 128 + ((c ^ (r & 7)) << 4),
                  Bg + (size_t)r * HID + k0 + c * 8, 16);
        }
    };

    prefetch(0, 0); CP_COMMIT();
    prefetch(1, 1); CP_COMMIT();

    for (int kt = 0; kt < KT; kt++) {
        CP_WAIT1();
        __syncthreads();                 // single barrier per stage
        if (kt + 2 < KT) prefetch((kt + 2) % 3, kt + 2);
        CP_COMMIT();

        uint32_t sA = sb + (kt % 3) * G2_STAGE;
        uint32_t sB = sA + 16384;
        int arow = (lane & 15);
        int achk = (lane >> 4);
#pragma unroll
        for (int s = 0; s < 4; s++) {
            int cb = s * 2 + achk;
            uint32_t aF[2][4], bF[8][2];
#pragma unroll
            for (int mt = 0; mt < 2; mt++) {
                int row = wm * 32 + mt * 16 + arow;
                LDSM4(aF[mt], sA + row * 128 + ((cb ^ (row & 7)) << 4));
            }
#pragma unroll
            for (int pr = 0; pr < 4; pr++) {
                int row = wn * 64 + pr * 16 + arow;
                uint32_t t[4];
                LDSM4(t, sB + row * 128 + ((cb ^ (row & 7)) << 4));
                bF[pr*2+0][0] = t[0]; bF[pr*2+0][1] = t[2];
                bF[pr*2+1][0] = t[1]; bF[pr*2+1][1] = t[3];
            }
#pragma unroll
            for (int mt = 0; mt < 2; mt++)
#pragma unroll
                for (int nt = 0; nt < 8; nt++)
                    MMA_F16(acc[mt][nt], aF[mt], bF[nt]);
        }
    }
    CP_WAIT0();

#pragma unroll
    for (int mt = 0; mt < 2; mt++) {
#pragma unroll
        for (int half = 0; half < 2; half++) {
            int r = row0 + wm * 32 + mt * 16 + half * 8 + gid;
            if (r >= n_e) continue;
            float w  = g_slot_w[base + r];
            int  tok = g_slot_tok[base + r];
            float* orow = out + (size_t)tok * DIM + col0;
#pragma unroll
            for (int nt = 0; nt < 8; nt++) {
                int c = wn * 64 + nt * 8 + ctid * 2;
                atomicAdd(&orow[c],     w * acc[mt][nt][half*2+0]);
                atomicAdd(&orow[c + 1], w * acc[mt][nt][half*2+1]);
            }
        }
    }
}

// ---------------- launch ----------------
extern "C" void kernel_launch(void* const* d_in, const int* in_sizes, int n_in,
                              void* d_out, int out_size)
{
    const float* x  = (const float*)d_in[0];
    const float* Wg = (const float*)d_in[1];
    const float* W1 = (const float*)d_in[2];
    const float* W3 = (const float*)d_in[3];
    const float* W2 = (const float*)d_in[4];
    float* out = (float*)d_out;
    int T = in_sizes[0] / DIM;

    cudaFuncSetAttribute(k_mma1, cudaFuncAttributeMaxDynamicSharedMemorySize, G1_SMEM);
    cudaFuncSetAttribute(k_mma2, cudaFuncAttributeMaxDynamicSharedMemorySize, G2_SMEM);

    k_zero_cnt<<<1, 32>>>();
    k_front<<<1536, 256>>>(x, Wg, out, T);
    k_transpose_all<<<12288, 256>>>(W1, W3, W2);
    k_scatter<<<(T + 255) / 256, 256>>>(T);

    k_mma1<<<dim3(HID/64, NE * (MAXT/128)), 256, G1_SMEM>>>();
    k_mma2<<<dim3(DIM/128, NE * (MAXT/128)), 256, G2_SMEM>>>(out);
}